// round 7
// baseline (speedup 1.0000x reference)
#include <cuda_runtime.h>
#include <cuda_fp16.h>
#include <cstdint>

// out = x @ (sum_k w_k W[ids_k])^T + sum_k w_k b[ids_k]
// Single-pass fp16 HMMA (validated rel_err ~2.9e-4 < 1e-3).
// This round: warp tile 64x64 (4 warps/CTA) for 4:1 MMA:LDSM issue ratio.
#define D_IN    1024
#define D_OUT   1024
#define M_TOTAL 4096
#define N_ADAPT 32

__device__ __half g_Xf[M_TOTAL * D_IN];
__device__ __half g_Wf[D_OUT * D_IN];
__device__ float  g_bmix[D_OUT];

// -------- PTX helpers (sm_80-era, valid for compute_103) --------------------
__device__ __forceinline__ uint32_t smem_u32(const void* p) {
    uint32_t a;
    asm("{ .reg .u64 t; cvta.to.shared.u64 t, %1; cvt.u32.u64 %0, t; }"
        : "=r"(a) : "l"(p));
    return a;
}
__device__ __forceinline__ void cp_async16(uint32_t dst, const void* src) {
    asm volatile("cp.async.cg.shared.global [%0], [%1], 16;"
                 :: "r"(dst), "l"(src) : "memory");
}
__device__ __forceinline__ void cp_commit() {
    asm volatile("cp.async.commit_group;" ::: "memory");
}
template <int N> __device__ __forceinline__ void cp_wait() {
    asm volatile("cp.async.wait_group %0;" :: "n"(N) : "memory");
}
__device__ __forceinline__ void ldsm_x4(uint32_t& r0, uint32_t& r1,
                                        uint32_t& r2, uint32_t& r3, uint32_t a) {
    asm volatile("ldmatrix.sync.aligned.m8n8.x4.shared.b16 {%0,%1,%2,%3}, [%4];"
                 : "=r"(r0), "=r"(r1), "=r"(r2), "=r"(r3) : "r"(a));
}
__device__ __forceinline__ void mma_f16(float* c, const uint32_t* a,
                                        const uint32_t* b) {
    asm volatile(
        "mma.sync.aligned.m16n8k16.row.col.f32.f16.f16.f32 "
        "{%0,%1,%2,%3}, {%4,%5,%6,%7}, {%8,%9}, {%0,%1,%2,%3};"
        : "+f"(c[0]), "+f"(c[1]), "+f"(c[2]), "+f"(c[3])
        : "r"(a[0]), "r"(a[1]), "r"(a[2]), "r"(a[3]), "r"(b[0]), "r"(b[1]));
}

// -------- ids dtype detection (JAX x64-off downcasts int64 -> int32) --------
__device__ __forceinline__ bool ids_look_i64(const void* idsptr, int K) {
    const int* p = (const int*)idsptr;
    bool odd_zero = true, even_valid = true;
    for (int k = 1; k < K; k += 2) if (p[k] != 0) odd_zero = false;
    for (int k = 0; k < K; k += 2) if (p[k] < 0 || p[k] >= N_ADAPT) even_valid = false;
    return odd_zero && even_valid;
}
__device__ __forceinline__ int load_id(const void* idsptr, int k, bool is64) {
    return is64 ? (int)((const long long*)idsptr)[k] : ((const int*)idsptr)[k];
}

// ---------------------------------------------------------------------------
// Fused prep: blocks [0,4096): x->fp16 ; [4096,5120): Wmix->fp16 ; 5120: bias
// ---------------------------------------------------------------------------
#define XBLKS 4096
#define WBLKS 1024
__global__ void prep_all_kernel(const float* __restrict__ x,
                                const float* __restrict__ W,
                                const float* __restrict__ b,
                                const void* __restrict__ ids,
                                const float* __restrict__ wts, int K) {
    const int bid = blockIdx.x;
    if (bid < XBLKS) {
        const int i = bid * 256 + threadIdx.x;   // float4 index into x
        float4 v = __ldg(&((const float4*)x)[i]);
        __half2 p0 = make_half2(__float2half_rn(v.x), __float2half_rn(v.y));
        __half2 p1 = make_half2(__float2half_rn(v.z), __float2half_rn(v.w));
        ((__half2*)g_Xf)[i * 2]     = p0;
        ((__half2*)g_Xf)[i * 2 + 1] = p1;
    } else if (bid < XBLKS + WBLKS) {
        const bool is64 = ids_look_i64(ids, K);
        const int i = (bid - XBLKS) * 256 + threadIdx.x;  // float4 index into Wmix
        const int OD4 = D_OUT * D_IN / 4;
        const float4* W4 = (const float4*)W;
        float4 acc = make_float4(0.f, 0.f, 0.f, 0.f);
        for (int k = 0; k < K; k++) {
            float w = __ldg(&wts[k]);
            long long id = load_id(ids, k, is64);
            float4 v = __ldg(&W4[id * (long long)OD4 + i]);
            acc.x += w * v.x; acc.y += w * v.y; acc.z += w * v.z; acc.w += w * v.w;
        }
        __half2 p0 = make_half2(__float2half_rn(acc.x), __float2half_rn(acc.y));
        __half2 p1 = make_half2(__float2half_rn(acc.z), __float2half_rn(acc.w));
        ((__half2*)g_Wf)[i * 2]     = p0;
        ((__half2*)g_Wf)[i * 2 + 1] = p1;
    } else {
        const bool is64 = ids_look_i64(ids, K);
        for (int i = threadIdx.x; i < D_OUT; i += 256) {
            float acc = 0.f;
            for (int k = 0; k < K; k++) {
                long long id = load_id(ids, k, is64);
                acc += __ldg(&wts[k]) * __ldg(&b[id * (long long)D_OUT + i]);
            }
            g_bmix[i] = acc;
        }
    }
}

// ---------------------------------------------------------------------------
// GEMM: C[m,n] = sum_d x[m,d] Wmix[n,d] + bmix[n]
// CTA tile 128x128, 4 warps (2Mx2N), warp tile 64x64, K-chunk 64.
// 3-stage cp.async pipeline, one __syncthreads per chunk (16 chunks).
// ---------------------------------------------------------------------------
#define MTILE 128
#define NTILE 128
#define KC    64
#define NCH   (D_IN / KC)           // 16
#define RSTR  72                    // padded row stride (halves): 144B rows
#define XOFF  0
#define WOFF  (128 * RSTR)
#define STAGE_ELEMS (2 * 128 * RSTR)    // 18432 halves = 36864 B
#define NSTAGE 3
#define SMEM_BYTES (NSTAGE * STAGE_ELEMS * 2)   // 110592 B

__global__ void __launch_bounds__(128, 2)
gemm_mma_kernel(float* __restrict__ C) {
    extern __shared__ __half sm[];
    const uint32_t sbase = smem_u32(sm);

    const int tid    = threadIdx.x;
    const int lane   = tid & 31;
    const int wid    = tid >> 5;        // 0..3
    const int warp_m = wid & 1;         // 2 warps in M (64 rows)
    const int warp_n = wid >> 1;        // 2 warps in N (64 cols)
    const int m0 = blockIdx.y * MTILE;
    const int n0 = blockIdx.x * NTILE;

    // global->smem: one full 128B row per thread per array (8 x 16B).
    const int lrow = tid;               // 0..127
    const __half* gX = g_Xf + (size_t)(m0 + lrow) * D_IN;
    const __half* gW = g_Wf + (size_t)(n0 + lrow) * D_IN;
    const uint32_t dst = (uint32_t)(lrow * RSTR) * 2;   // stage byte offset

    auto load_stage = [&](int c) {
        const uint32_t sb = sbase + (uint32_t)(c % NSTAGE) * STAGE_ELEMS * 2;
        const size_t go = (size_t)c * KC;
#pragma unroll
        for (int j = 0; j < 8; j++) {
            const uint32_t d = dst + j * 16;
            cp_async16(sb + XOFF * 2 + d, gX + go + j * 8);
            cp_async16(sb + WOFF * 2 + d, gW + go + j * 8);
        }
    };

    // ldmatrix lane mapping (validated layout from R4-R6)
    const int a_row = (lane & 15);
    const int a_kof = (lane >> 4) * 8;
    const int b_row = ((lane >> 4) << 3) + (lane & 7);
    const int b_kof = ((lane >> 3) & 1) * 8;

    float acc[4][8][4];
#pragma unroll
    for (int i = 0; i < 4; i++)
#pragma unroll
        for (int j = 0; j < 8; j++)
#pragma unroll
            for (int q = 0; q < 4; q++) acc[i][j][q] = 0.f;

    load_stage(0); cp_commit();
    load_stage(1); cp_commit();

    for (int c = 0; c < NCH; c++) {
        cp_wait<NSTAGE - 2>();      // stage c resident
        __syncthreads();

        const uint32_t sb = sbase + (uint32_t)(c % NSTAGE) * STAGE_ELEMS * 2;
#pragma unroll
        for (int ks = 0; ks < KC / 16; ks++) {
            const int k0 = ks * 16;
            uint32_t af[4][4];
#pragma unroll
            for (int mf = 0; mf < 4; mf++) {
                const uint32_t ro =
                    (uint32_t)((warp_m * 64 + mf * 16 + a_row) * RSTR + k0 + a_kof) * 2;
                ldsm_x4(af[mf][0], af[mf][1], af[mf][2], af[mf][3], sb + XOFF * 2 + ro);
            }
            uint32_t bf[8][2];
#pragma unroll
            for (int ng = 0; ng < 4; ng++) {
                const uint32_t ro =
                    (uint32_t)((warp_n * 64 + ng * 16 + b_row) * RSTR + k0 + b_kof) * 2;
                uint32_t r0, r1, r2, r3;
                ldsm_x4(r0, r1, r2, r3, sb + WOFF * 2 + ro);
                bf[ng * 2][0] = r0; bf[ng * 2][1] = r1;
                bf[ng * 2 + 1][0] = r2; bf[ng * 2 + 1][1] = r3;
            }
#pragma unroll
            for (int mf = 0; mf < 4; mf++)
#pragma unroll
                for (int nf = 0; nf < 8; nf++)
                    mma_f16(acc[mf][nf], af[mf], bf[nf]);
        }

        if (c + NSTAGE - 1 < NCH) load_stage(c + NSTAGE - 1);
        cp_commit();    // unconditional: empty tail groups keep wait<> sound
    }

    // epilogue: add bias, store float2 pairs
    const int g = lane >> 2;
    const int cpair = (lane & 3) * 2;
#pragma unroll
    for (int mf = 0; mf < 4; mf++) {
        const int row = m0 + warp_m * 64 + mf * 16 + g;
#pragma unroll
        for (int nf = 0; nf < 8; nf++) {
            const int col = n0 + warp_n * 64 + nf * 8 + cpair;
            const float b0 = __ldg(&g_bmix[col]);
            const float b1 = __ldg(&g_bmix[col + 1]);
            float2 v0 = make_float2(acc[mf][nf][0] + b0, acc[mf][nf][1] + b1);
            float2 v1 = make_float2(acc[mf][nf][2] + b0, acc[mf][nf][3] + b1);
            *(float2*)(C + (size_t)row * D_OUT + col) = v0;
            *(float2*)(C + (size_t)(row + 8) * D_OUT + col) = v1;
        }
    }
}

// ---------------------------------------------------------------------------
extern "C" void kernel_launch(void* const* d_in, const int* in_sizes, int n_in,
                              void* d_out, int out_size) {
    const float* x   = (const float*)d_in[0];
    const float* W   = (const float*)d_in[1];
    const float* b   = (const float*)d_in[2];
    const void*  ids = d_in[3];
    const float* wts = (const float*)d_in[4];
    const int K = in_sizes[3];

    cudaFuncSetAttribute(gemm_mma_kernel,
                         cudaFuncAttributeMaxDynamicSharedMemorySize, SMEM_BYTES);

    prep_all_kernel<<<XBLKS + WBLKS + 1, 256>>>(x, W, b, ids, wts, K);

    dim3 grid(D_OUT / NTILE, M_TOTAL / MTILE);  // (8, 32) = 256 CTAs
    gemm_mma_kernel<<<grid, 128, SMEM_BYTES>>>((float*)d_out);
}

// round 8
// speedup vs baseline: 1.0975x; 1.0975x over previous
#include <cuda_runtime.h>
#include <cuda_fp16.h>
#include <cstdint>

// out = x @ (sum_k w_k W[ids_k])^T + sum_k w_k b[ids_k]
// Single-pass fp16 HMMA (validated rel_err 2.93e-4 < 1e-3).
// R8: R6 config (256thr, warp 64x32, 2 CTA/SM) + register fragment
// double-buffering across ks-steps + earlier cp.async issue.
#define D_IN    1024
#define D_OUT   1024
#define M_TOTAL 4096
#define N_ADAPT 32

__device__ __half g_Xf[M_TOTAL * D_IN];
__device__ __half g_Wf[D_OUT * D_IN];
__device__ float  g_bmix[D_OUT];

// -------- PTX helpers (sm_80-era, valid for compute_103) --------------------
__device__ __forceinline__ uint32_t smem_u32(const void* p) {
    uint32_t a;
    asm("{ .reg .u64 t; cvta.to.shared.u64 t, %1; cvt.u32.u64 %0, t; }"
        : "=r"(a) : "l"(p));
    return a;
}
__device__ __forceinline__ void cp_async16(uint32_t dst, const void* src) {
    asm volatile("cp.async.cg.shared.global [%0], [%1], 16;"
                 :: "r"(dst), "l"(src) : "memory");
}
__device__ __forceinline__ void cp_commit() {
    asm volatile("cp.async.commit_group;" ::: "memory");
}
template <int N> __device__ __forceinline__ void cp_wait() {
    asm volatile("cp.async.wait_group %0;" :: "n"(N) : "memory");
}
__device__ __forceinline__ void ldsm_x4(uint32_t& r0, uint32_t& r1,
                                        uint32_t& r2, uint32_t& r3, uint32_t a) {
    asm volatile("ldmatrix.sync.aligned.m8n8.x4.shared.b16 {%0,%1,%2,%3}, [%4];"
                 : "=r"(r0), "=r"(r1), "=r"(r2), "=r"(r3) : "r"(a));
}
__device__ __forceinline__ void mma_f16(float* c, const uint32_t* a,
                                        const uint32_t* b) {
    asm volatile(
        "mma.sync.aligned.m16n8k16.row.col.f32.f16.f16.f32 "
        "{%0,%1,%2,%3}, {%4,%5,%6,%7}, {%8,%9}, {%0,%1,%2,%3};"
        : "+f"(c[0]), "+f"(c[1]), "+f"(c[2]), "+f"(c[3])
        : "r"(a[0]), "r"(a[1]), "r"(a[2]), "r"(a[3]), "r"(b[0]), "r"(b[1]));
}

// -------- ids dtype detection (JAX x64-off downcasts int64 -> int32) --------
__device__ __forceinline__ bool ids_look_i64(const void* idsptr, int K) {
    const int* p = (const int*)idsptr;
    bool odd_zero = true, even_valid = true;
    for (int k = 1; k < K; k += 2) if (p[k] != 0) odd_zero = false;
    for (int k = 0; k < K; k += 2) if (p[k] < 0 || p[k] >= N_ADAPT) even_valid = false;
    return odd_zero && even_valid;
}
__device__ __forceinline__ int load_id(const void* idsptr, int k, bool is64) {
    return is64 ? (int)((const long long*)idsptr)[k] : ((const int*)idsptr)[k];
}

// ---------------------------------------------------------------------------
// Fused prep: blocks [0,4096): x->fp16 ; [4096,5120): Wmix->fp16 ; 5120: bias
// ---------------------------------------------------------------------------
#define XBLKS 4096
#define WBLKS 1024
__global__ void prep_all_kernel(const float* __restrict__ x,
                                const float* __restrict__ W,
                                const float* __restrict__ b,
                                const void* __restrict__ ids,
                                const float* __restrict__ wts, int K) {
    const int bid = blockIdx.x;
    if (bid < XBLKS) {
        const int i = bid * 256 + threadIdx.x;   // float4 index into x
        float4 v = __ldg(&((const float4*)x)[i]);
        __half2 p0 = make_half2(__float2half_rn(v.x), __float2half_rn(v.y));
        __half2 p1 = make_half2(__float2half_rn(v.z), __float2half_rn(v.w));
        ((__half2*)g_Xf)[i * 2]     = p0;
        ((__half2*)g_Xf)[i * 2 + 1] = p1;
    } else if (bid < XBLKS + WBLKS) {
        const bool is64 = ids_look_i64(ids, K);
        const int i = (bid - XBLKS) * 256 + threadIdx.x;  // float4 index into Wmix
        const int OD4 = D_OUT * D_IN / 4;
        const float4* W4 = (const float4*)W;
        float4 acc = make_float4(0.f, 0.f, 0.f, 0.f);
        for (int k = 0; k < K; k++) {
            float w = __ldg(&wts[k]);
            long long id = load_id(ids, k, is64);
            float4 v = __ldg(&W4[id * (long long)OD4 + i]);
            acc.x += w * v.x; acc.y += w * v.y; acc.z += w * v.z; acc.w += w * v.w;
        }
        __half2 p0 = make_half2(__float2half_rn(acc.x), __float2half_rn(acc.y));
        __half2 p1 = make_half2(__float2half_rn(acc.z), __float2half_rn(acc.w));
        ((__half2*)g_Wf)[i * 2]     = p0;
        ((__half2*)g_Wf)[i * 2 + 1] = p1;
    } else {
        const bool is64 = ids_look_i64(ids, K);
        for (int i = threadIdx.x; i < D_OUT; i += 256) {
            float acc = 0.f;
            for (int k = 0; k < K; k++) {
                long long id = load_id(ids, k, is64);
                acc += __ldg(&wts[k]) * __ldg(&b[id * (long long)D_OUT + i]);
            }
            g_bmix[i] = acc;
        }
    }
}

// ---------------------------------------------------------------------------
// GEMM: C[m,n] = sum_d x[m,d] Wmix[n,d] + bmix[n]
// CTA 128x128, 8 warps (2Mx4N), warp tile 64x32, K-chunk 64, 3-stage cp.async.
// Register fragment double-buffering across the 4 ks-steps of each chunk.
// ---------------------------------------------------------------------------
#define MTILE 128
#define NTILE 128
#define KC    64
#define NCH   (D_IN / KC)           // 16
#define RSTR  72                    // padded row stride (halves): 144B rows
#define XOFF  0
#define WOFF  (128 * RSTR)
#define STAGE_ELEMS (2 * 128 * RSTR)    // 18432 halves = 36864 B
#define NSTAGE 3
#define SMEM_BYTES (NSTAGE * STAGE_ELEMS * 2)   // 110592 B

__global__ void __launch_bounds__(256, 2)
gemm_mma_kernel(float* __restrict__ C) {
    extern __shared__ __half sm[];
    const uint32_t sbase = smem_u32(sm);

    const int tid    = threadIdx.x;
    const int lane   = tid & 31;
    const int wid    = tid >> 5;
    const int warp_m = wid & 1;         // 2 warps in M (64 rows)
    const int warp_n = wid >> 1;        // 4 warps in N (32 cols)
    const int m0 = blockIdx.y * MTILE;
    const int n0 = blockIdx.x * NTILE;

    // global->smem: row = tid>>1 (0..127); 4 x 16B chunks per thread per array.
    const int lrow = tid >> 1;
    const int lkh  = (tid & 1) * 32;
    const __half* gX = g_Xf + (size_t)(m0 + lrow) * D_IN + lkh;
    const __half* gW = g_Wf + (size_t)(n0 + lrow) * D_IN + lkh;
    const uint32_t dst = (uint32_t)(lrow * RSTR + lkh) * 2;

    auto load_stage = [&](int c) {
        const uint32_t sb = sbase + (uint32_t)(c % NSTAGE) * STAGE_ELEMS * 2;
        const size_t go = (size_t)c * KC;
#pragma unroll
        for (int j = 0; j < 4; j++) {
            const uint32_t d = dst + j * 16;
            cp_async16(sb + XOFF * 2 + d, gX + go + j * 8);
            cp_async16(sb + WOFF * 2 + d, gW + go + j * 8);
        }
    };

    // ldmatrix lane mapping (validated layout R4-R6)
    const int a_row = (lane & 15);
    const int a_kof = (lane >> 4) * 8;
    const int b_row = ((lane >> 4) << 3) + (lane & 7);
    const int b_kof = ((lane >> 3) & 1) * 8;

    // per-thread base byte offsets inside a stage (k0 added per ks)
    const uint32_t aro = (uint32_t)((warp_m * 64 + a_row) * RSTR + a_kof) * 2;
    const uint32_t bro = (uint32_t)((warp_n * 32 + b_row) * RSTR + b_kof) * 2;

    float acc[4][4][4];
#pragma unroll
    for (int i = 0; i < 4; i++)
#pragma unroll
        for (int j = 0; j < 4; j++)
#pragma unroll
            for (int q = 0; q < 4; q++) acc[i][j][q] = 0.f;

    uint32_t af[2][4][4];   // [buf][mf][reg]
    uint32_t bf[2][4][2];   // [buf][nf][reg]

    auto ld_frags = [&](int buf, uint32_t sb, int k0) {
#pragma unroll
        for (int mf = 0; mf < 4; mf++) {
            const uint32_t ro = aro + (uint32_t)(mf * 16 * RSTR + k0) * 2;
            ldsm_x4(af[buf][mf][0], af[buf][mf][1], af[buf][mf][2], af[buf][mf][3],
                    sb + XOFF * 2 + ro);
        }
#pragma unroll
        for (int ng = 0; ng < 2; ng++) {
            const uint32_t ro = bro + (uint32_t)(ng * 16 * RSTR + k0) * 2;
            uint32_t r0, r1, r2, r3;
            ldsm_x4(r0, r1, r2, r3, sb + WOFF * 2 + ro);
            bf[buf][ng * 2][0] = r0;     bf[buf][ng * 2][1] = r1;
            bf[buf][ng * 2 + 1][0] = r2; bf[buf][ng * 2 + 1][1] = r3;
        }
    };

    load_stage(0); cp_commit();
    load_stage(1); cp_commit();

    for (int c = 0; c < NCH; c++) {
        cp_wait<NSTAGE - 2>();      // stage c resident (per-thread)
        __syncthreads();            // visibility + slot-reuse safety

        // issue next stage load EARLY (slot (c+2)%3 == slot of chunk c-1,
        // which all warps finished reading before the barrier above)
        if (c + NSTAGE - 1 < NCH) load_stage(c + NSTAGE - 1);
        cp_commit();

        const uint32_t sb = sbase + (uint32_t)(c % NSTAGE) * STAGE_ELEMS * 2;
        ld_frags(0, sb, 0);
#pragma unroll
        for (int ks = 0; ks < KC / 16; ks++) {
            const int cur = ks & 1;
            if (ks < KC / 16 - 1) ld_frags(cur ^ 1, sb, (ks + 1) * 16);
#pragma unroll
            for (int mf = 0; mf < 4; mf++)
#pragma unroll
                for (int nf = 0; nf < 4; nf++)
                    mma_f16(acc[mf][nf], af[cur][mf], bf[cur][nf]);
        }
    }

    // epilogue: add bias, store float2 pairs
    const int g = lane >> 2;
    const int cpair = (lane & 3) * 2;
#pragma unroll
    for (int mf = 0; mf < 4; mf++) {
        const int row = m0 + warp_m * 64 + mf * 16 + g;
#pragma unroll
        for (int nf = 0; nf < 4; nf++) {
            const int col = n0 + warp_n * 32 + nf * 8 + cpair;
            const float b0 = __ldg(&g_bmix[col]);
            const float b1 = __ldg(&g_bmix[col + 1]);
            float2 v0 = make_float2(acc[mf][nf][0] + b0, acc[mf][nf][1] + b1);
            float2 v1 = make_float2(acc[mf][nf][2] + b0, acc[mf][nf][3] + b1);
            *(float2*)(C + (size_t)row * D_OUT + col) = v0;
            *(float2*)(C + (size_t)(row + 8) * D_OUT + col) = v1;
        }
    }
}

// ---------------------------------------------------------------------------
extern "C" void kernel_launch(void* const* d_in, const int* in_sizes, int n_in,
                              void* d_out, int out_size) {
    const float* x   = (const float*)d_in[0];
    const float* W   = (const float*)d_in[1];
    const float* b   = (const float*)d_in[2];
    const void*  ids = d_in[3];
    const float* wts = (const float*)d_in[4];
    const int K = in_sizes[3];

    cudaFuncSetAttribute(gemm_mma_kernel,
                         cudaFuncAttributeMaxDynamicSharedMemorySize, SMEM_BYTES);

    prep_all_kernel<<<XBLKS + WBLKS + 1, 256>>>(x, W, b, ids, wts, K);

    dim3 grid(D_OUT / NTILE, M_TOTAL / MTILE);  // (8, 32) = 256 CTAs
    gemm_mma_kernel<<<grid, 256, SMEM_BYTES>>>((float*)d_out);
}

// round 9
// speedup vs baseline: 1.3994x; 1.2751x over previous
#include <cuda_runtime.h>
#include <cuda_fp16.h>
#include <cstdint>

// out = x @ (sum_k w_k W[ids_k])^T + sum_k w_k b[ids_k]
// Single-pass fp16 HMMA (validated rel_err 2.93e-4 < 1e-3).
// R9: 512-thread CTA, 16 warps of 32x32 -> 32 warps/SM (2 CTA/SM) for
// latency hiding. R6 loop ordering retained (measured best).
#define D_IN    1024
#define D_OUT   1024
#define M_TOTAL 4096
#define N_ADAPT 32

__device__ __half g_Xf[M_TOTAL * D_IN];
__device__ __half g_Wf[D_OUT * D_IN];
__device__ float  g_bmix[D_OUT];

// -------- PTX helpers (sm_80-era, valid for compute_103) --------------------
__device__ __forceinline__ uint32_t smem_u32(const void* p) {
    uint32_t a;
    asm("{ .reg .u64 t; cvta.to.shared.u64 t, %1; cvt.u32.u64 %0, t; }"
        : "=r"(a) : "l"(p));
    return a;
}
__device__ __forceinline__ void cp_async16(uint32_t dst, const void* src) {
    asm volatile("cp.async.cg.shared.global [%0], [%1], 16;"
                 :: "r"(dst), "l"(src) : "memory");
}
__device__ __forceinline__ void cp_commit() {
    asm volatile("cp.async.commit_group;" ::: "memory");
}
template <int N> __device__ __forceinline__ void cp_wait() {
    asm volatile("cp.async.wait_group %0;" :: "n"(N) : "memory");
}
__device__ __forceinline__ void ldsm_x4(uint32_t& r0, uint32_t& r1,
                                        uint32_t& r2, uint32_t& r3, uint32_t a) {
    asm volatile("ldmatrix.sync.aligned.m8n8.x4.shared.b16 {%0,%1,%2,%3}, [%4];"
                 : "=r"(r0), "=r"(r1), "=r"(r2), "=r"(r3) : "r"(a));
}
__device__ __forceinline__ void mma_f16(float* c, const uint32_t* a,
                                        const uint32_t* b) {
    asm volatile(
        "mma.sync.aligned.m16n8k16.row.col.f32.f16.f16.f32 "
        "{%0,%1,%2,%3}, {%4,%5,%6,%7}, {%8,%9}, {%0,%1,%2,%3};"
        : "+f"(c[0]), "+f"(c[1]), "+f"(c[2]), "+f"(c[3])
        : "r"(a[0]), "r"(a[1]), "r"(a[2]), "r"(a[3]), "r"(b[0]), "r"(b[1]));
}

// -------- ids dtype detection (JAX x64-off downcasts int64 -> int32) --------
__device__ __forceinline__ bool ids_look_i64(const void* idsptr, int K) {
    const int* p = (const int*)idsptr;
    bool odd_zero = true, even_valid = true;
    for (int k = 1; k < K; k += 2) if (p[k] != 0) odd_zero = false;
    for (int k = 0; k < K; k += 2) if (p[k] < 0 || p[k] >= N_ADAPT) even_valid = false;
    return odd_zero && even_valid;
}
__device__ __forceinline__ int load_id(const void* idsptr, int k, bool is64) {
    return is64 ? (int)((const long long*)idsptr)[k] : ((const int*)idsptr)[k];
}

// ---------------------------------------------------------------------------
// Fused prep: blocks [0,4096): x->fp16 ; [4096,5120): Wmix->fp16 ; 5120: bias
// ---------------------------------------------------------------------------
#define XBLKS 4096
#define WBLKS 1024
__global__ void prep_all_kernel(const float* __restrict__ x,
                                const float* __restrict__ W,
                                const float* __restrict__ b,
                                const void* __restrict__ ids,
                                const float* __restrict__ wts, int K) {
    const int bid = blockIdx.x;
    if (bid < XBLKS) {
        const int i = bid * 256 + threadIdx.x;   // float4 index into x
        float4 v = __ldg(&((const float4*)x)[i]);
        __half2 p0 = make_half2(__float2half_rn(v.x), __float2half_rn(v.y));
        __half2 p1 = make_half2(__float2half_rn(v.z), __float2half_rn(v.w));
        ((__half2*)g_Xf)[i * 2]     = p0;
        ((__half2*)g_Xf)[i * 2 + 1] = p1;
    } else if (bid < XBLKS + WBLKS) {
        const bool is64 = ids_look_i64(ids, K);
        const int i = (bid - XBLKS) * 256 + threadIdx.x;  // float4 index into Wmix
        const int OD4 = D_OUT * D_IN / 4;
        const float4* W4 = (const float4*)W;
        float4 acc = make_float4(0.f, 0.f, 0.f, 0.f);
        for (int k = 0; k < K; k++) {
            float w = __ldg(&wts[k]);
            long long id = load_id(ids, k, is64);
            float4 v = __ldg(&W4[id * (long long)OD4 + i]);
            acc.x += w * v.x; acc.y += w * v.y; acc.z += w * v.z; acc.w += w * v.w;
        }
        __half2 p0 = make_half2(__float2half_rn(acc.x), __float2half_rn(acc.y));
        __half2 p1 = make_half2(__float2half_rn(acc.z), __float2half_rn(acc.w));
        ((__half2*)g_Wf)[i * 2]     = p0;
        ((__half2*)g_Wf)[i * 2 + 1] = p1;
    } else {
        const bool is64 = ids_look_i64(ids, K);
        for (int i = threadIdx.x; i < D_OUT; i += 256) {
            float acc = 0.f;
            for (int k = 0; k < K; k++) {
                long long id = load_id(ids, k, is64);
                acc += __ldg(&wts[k]) * __ldg(&b[id * (long long)D_OUT + i]);
            }
            g_bmix[i] = acc;
        }
    }
}

// ---------------------------------------------------------------------------
// GEMM: C[m,n] = sum_d x[m,d] Wmix[n,d] + bmix[n]
// CTA 128x128, 16 warps (4Mx4N), warp tile 32x32, K-chunk 64, 3-stage cp.async.
// 512 threads, target <=64 regs -> 2 CTA/SM = 32 warps/SM.
// ---------------------------------------------------------------------------
#define MTILE 128
#define NTILE 128
#define KC    64
#define NCH   (D_IN / KC)           // 16
#define RSTR  72                    // padded row stride (halves): 144B rows
#define XOFF  0
#define WOFF  (128 * RSTR)
#define STAGE_ELEMS (2 * 128 * RSTR)    // 18432 halves = 36864 B
#define NSTAGE 3
#define SMEM_BYTES (NSTAGE * STAGE_ELEMS * 2)   // 110592 B

__global__ void __launch_bounds__(512, 2)
gemm_mma_kernel(float* __restrict__ C) {
    extern __shared__ __half sm[];
    const uint32_t sbase = smem_u32(sm);

    const int tid    = threadIdx.x;
    const int lane   = tid & 31;
    const int wid    = tid >> 5;        // 0..15
    const int warp_m = wid & 3;         // 4 warps in M (32 rows each)
    const int warp_n = wid >> 2;        // 4 warps in N (32 cols each)
    const int m0 = blockIdx.y * MTILE;
    const int n0 = blockIdx.x * NTILE;

    // global->smem: 4 threads per 128B row; each thread 2 x 16B per array.
    const int lrow = tid >> 2;              // 0..127
    const int lkh  = (tid & 3) * 16;        // half offset: 0,16,32,48
    const __half* gX = g_Xf + (size_t)(m0 + lrow) * D_IN + lkh;
    const __half* gW = g_Wf + (size_t)(n0 + lrow) * D_IN + lkh;
    const uint32_t dst = (uint32_t)(lrow * RSTR + lkh) * 2;

    auto load_stage = [&](int c) {
        const uint32_t sb = sbase + (uint32_t)(c % NSTAGE) * STAGE_ELEMS * 2;
        const size_t go = (size_t)c * KC;
#pragma unroll
        for (int j = 0; j < 2; j++) {
            const uint32_t d = dst + j * 16;
            cp_async16(sb + XOFF * 2 + d, gX + go + j * 8);
            cp_async16(sb + WOFF * 2 + d, gW + go + j * 8);
        }
    };

    // ldmatrix lane mapping (validated layout R4-R8)
    const int a_row = (lane & 15);
    const int a_kof = (lane >> 4) * 8;
    const int b_row = ((lane >> 4) << 3) + (lane & 7);
    const int b_kof = ((lane >> 3) & 1) * 8;

    // per-thread base byte offsets inside a stage
    const uint32_t aro = (uint32_t)((warp_m * 32 + a_row) * RSTR + a_kof) * 2;
    const uint32_t bro = (uint32_t)((warp_n * 32 + b_row) * RSTR + b_kof) * 2;

    float acc[2][4][4];
#pragma unroll
    for (int i = 0; i < 2; i++)
#pragma unroll
        for (int j = 0; j < 4; j++)
#pragma unroll
            for (int q = 0; q < 4; q++) acc[i][j][q] = 0.f;

    load_stage(0); cp_commit();
    load_stage(1); cp_commit();

    for (int c = 0; c < NCH; c++) {
        cp_wait<NSTAGE - 2>();      // stage c resident
        __syncthreads();

        const uint32_t sb = sbase + (uint32_t)(c % NSTAGE) * STAGE_ELEMS * 2;
#pragma unroll
        for (int ks = 0; ks < KC / 16; ks++) {
            const int k0 = ks * 16;
            uint32_t af[2][4];
#pragma unroll
            for (int mf = 0; mf < 2; mf++) {
                const uint32_t ro = aro + (uint32_t)(mf * 16 * RSTR + k0) * 2;
                ldsm_x4(af[mf][0], af[mf][1], af[mf][2], af[mf][3],
                        sb + XOFF * 2 + ro);
            }
            uint32_t bf[4][2];
#pragma unroll
            for (int ng = 0; ng < 2; ng++) {
                const uint32_t ro = bro + (uint32_t)(ng * 16 * RSTR + k0) * 2;
                uint32_t r0, r1, r2, r3;
                ldsm_x4(r0, r1, r2, r3, sb + WOFF * 2 + ro);
                bf[ng * 2][0] = r0;     bf[ng * 2][1] = r1;
                bf[ng * 2 + 1][0] = r2; bf[ng * 2 + 1][1] = r3;
            }
#pragma unroll
            for (int mf = 0; mf < 2; mf++)
#pragma unroll
                for (int nf = 0; nf < 4; nf++)
                    mma_f16(acc[mf][nf], af[mf], bf[nf]);
        }

        if (c + NSTAGE - 1 < NCH) load_stage(c + NSTAGE - 1);
        cp_commit();    // unconditional: empty tail groups keep wait<> sound
    }

    // epilogue: add bias, store float2 pairs
    const int g = lane >> 2;
    const int cpair = (lane & 3) * 2;
#pragma unroll
    for (int mf = 0; mf < 2; mf++) {
        const int row = m0 + warp_m * 32 + mf * 16 + g;
#pragma unroll
        for (int nf = 0; nf < 4; nf++) {
            const int col = n0 + warp_n * 32 + nf * 8 + cpair;
            const float b0 = __ldg(&g_bmix[col]);
            const float b1 = __ldg(&g_bmix[col + 1]);
            float2 v0 = make_float2(acc[mf][nf][0] + b0, acc[mf][nf][1] + b1);
            float2 v1 = make_float2(acc[mf][nf][2] + b0, acc[mf][nf][3] + b1);
            *(float2*)(C + (size_t)row * D_OUT + col) = v0;
            *(float2*)(C + (size_t)(row + 8) * D_OUT + col) = v1;
        }
    }
}

// ---------------------------------------------------------------------------
extern "C" void kernel_launch(void* const* d_in, const int* in_sizes, int n_in,
                              void* d_out, int out_size) {
    const float* x   = (const float*)d_in[0];
    const float* W   = (const float*)d_in[1];
    const float* b   = (const float*)d_in[2];
    const void*  ids = d_in[3];
    const float* wts = (const float*)d_in[4];
    const int K = in_sizes[3];

    cudaFuncSetAttribute(gemm_mma_kernel,
                         cudaFuncAttributeMaxDynamicSharedMemorySize, SMEM_BYTES);

    prep_all_kernel<<<XBLKS + WBLKS + 1, 256>>>(x, W, b, ids, wts, K);

    dim3 grid(D_OUT / NTILE, M_TOTAL / MTILE);  // (8, 32) = 256 CTAs
    gemm_mma_kernel<<<grid, 512, SMEM_BYTES>>>((float*)d_out);
}